// round 6
// baseline (speedup 1.0000x reference)
#include <cuda_runtime.h>
#include <cuda_bf16.h>

#define N_ITEMS 100000
#define HID 128
#define NNZ_N 1600000
#define RPB 8      // output rows per spmm block (100000 % 8 == 0)
#define CH 256     // edge staging chunk

// Intermediate: support = X @ W^T + b   (51.2 MB device-global scratch)
__device__ float g_support[(size_t)N_ITEMS * HID];

// Packed fp32x2 FMA (2 FMAs / instruction on the fma pipe).
__device__ __forceinline__ unsigned long long ffma2(unsigned long long a,
                                                    unsigned long long b,
                                                    unsigned long long c) {
    unsigned long long d;
    asm("fma.rn.f32x2 %0, %1, %2, %3;" : "=l"(d) : "l"(a), "l"(b), "l"(c));
    return d;
}

// ---------------------------------------------------------------------------
// GEMM: support[n][c] = sum_k X[n][k] * W[c][k] + bias[c]
// Tile: 128 rows x 128 cols per block, 256 threads, 8x8 register tile/thread.
// Packing is along K: acc holds {even-k partial, odd-k partial}; both operand
// k-pairs are contiguous in memory -> plain LDS.64, no repack instructions.
// ---------------------------------------------------------------------------
extern "C" __global__ void __launch_bounds__(256)
gemm_kernel(const float* __restrict__ X, const float* __restrict__ W,
            const float* __restrict__ bias, int nrows)
{
    extern __shared__ unsigned long long smem[];
    unsigned long long* xs = smem;             // [64 k-pairs][128 rows]
    unsigned long long* ws = smem + 64 * 128;  // [64 k-pairs][128 cols]

    const int tid  = threadIdx.x;
    const int row0 = blockIdx.x * 128;

    // Fill: thread t owns tile row/col r = t/2, k4 range selected by t&1.
    // STS pattern is conflict-free (adjacent lanes -> adjacent 8B in r).
    {
        const int r      = tid >> 1;
        const int k4base = (tid & 1) * 16;
        const int grow   = row0 + r;
        const bool xok   = grow < nrows;
        const float4* xr4 = (const float4*)(X + (size_t)grow * HID);
        const float4* wr4 = (const float4*)(W + (size_t)r * HID);
        #pragma unroll
        for (int j = 0; j < 16; j++) {
            int k4 = k4base + j;
            float4 xv = xok ? xr4[k4] : make_float4(0.f, 0.f, 0.f, 0.f);
            float4 wv = wr4[k4];
            float2 x0 = make_float2(xv.x, xv.y);
            float2 x1 = make_float2(xv.z, xv.w);
            float2 w0 = make_float2(wv.x, wv.y);
            float2 w1 = make_float2(wv.z, wv.w);
            xs[(2 * k4)     * 128 + r] = *(unsigned long long*)&x0;
            xs[(2 * k4 + 1) * 128 + r] = *(unsigned long long*)&x1;
            ws[(2 * k4)     * 128 + r] = *(unsigned long long*)&w0;
            ws[(2 * k4 + 1) * 128 + r] = *(unsigned long long*)&w1;
        }
    }
    __syncthreads();

    const int tx = tid & 15;   // col group: c = tx + 16*j  (contiguous per warp)
    const int ty = tid >> 4;   // row group: r = ty*8 + i   (broadcast per warp)

    unsigned long long acc[8][8];
    #pragma unroll
    for (int i = 0; i < 8; i++)
        #pragma unroll
        for (int j = 0; j < 8; j++)
            acc[i][j] = 0ull;  // {0.f, 0.f}

    for (int k2 = 0; k2 < 64; k2++) {
        unsigned long long xv[8], wv[8];
        #pragma unroll
        for (int i = 0; i < 8; i++) xv[i] = xs[k2 * 128 + ty * 8 + i];
        #pragma unroll
        for (int j = 0; j < 8; j++) wv[j] = ws[k2 * 128 + tx + j * 16];
        #pragma unroll
        for (int i = 0; i < 8; i++)
            #pragma unroll
            for (int j = 0; j < 8; j++)
                acc[i][j] = ffma2(xv[i], wv[j], acc[i][j]);
    }

    // Epilogue: fold the two k-parity partials, add bias, store fp32.
    float bv[8];
    #pragma unroll
    for (int j = 0; j < 8; j++) bv[j] = bias[tx + j * 16];

    #pragma unroll
    for (int i = 0; i < 8; i++) {
        int row = row0 + ty * 8 + i;
        if (row < nrows) {
            #pragma unroll
            for (int j = 0; j < 8; j++) {
                float2 a = *(float2*)&acc[i][j];
                g_support[(size_t)row * HID + (tx + j * 16)] = a.x + a.y + bv[j];
            }
        }
    }
}

// ---------------------------------------------------------------------------
// SpMM: out = A_coo @ support, adj_rows SORTED -> segment by output rows.
// Each block owns rows [r0, r0+RPB); edge range found by binary search.
// No atomics, every output row written exactly once (empty rows get 0).
// ---------------------------------------------------------------------------
__device__ __forceinline__ int lower_bound_dev(const int* __restrict__ a,
                                               int n, int key) {
    int lo = 0, hi = n;
    while (lo < hi) {
        int mid = (lo + hi) >> 1;
        if (__ldg(a + mid) < key) lo = mid + 1; else hi = mid;
    }
    return lo;
}

extern "C" __global__ void __launch_bounds__(128)
spmm_kernel(const int* __restrict__ rows, const int* __restrict__ cols,
            const float* __restrict__ vals, float* __restrict__ out)
{
    const int h  = threadIdx.x;            // column (one per thread, 128B/warp gather)
    const int r0 = blockIdx.x * RPB;

    __shared__ int   s_lo, s_hi;
    __shared__ int   s_r[CH];
    __shared__ int   s_c[CH];
    __shared__ float s_v[CH];

    if (h == 0) {
        s_lo = lower_bound_dev(rows, NNZ_N, r0);
        s_hi = lower_bound_dev(rows, NNZ_N, r0 + RPB);
    }
    __syncthreads();
    const int lo = s_lo, hi = s_hi;

    int   cur = r0;
    float acc = 0.f;

    for (int base = lo; base < hi; base += CH) {
        int cnt = min(CH, hi - base);
        for (int i = h; i < cnt; i += 128) {
            s_r[i] = rows[base + i];
            s_c[i] = cols[base + i];
            s_v[i] = vals[base + i];
        }
        __syncthreads();

        int i = 0;
        // 8-wide batches: all 8 gathers issue before use -> MLP=8/warp.
        for (; i + 8 <= cnt; i += 8) {
            float sv[8], vv[8]; int er[8];
            #pragma unroll
            for (int u = 0; u < 8; u++) {
                er[u] = s_r[i + u];
                vv[u] = s_v[i + u];
                sv[u] = __ldg(&g_support[(size_t)s_c[i + u] * HID + h]);
            }
            #pragma unroll
            for (int u = 0; u < 8; u++) {
                int r = er[u];
                while (cur < r) {           // flush finished row(s); skipped rows -> 0
                    out[(size_t)cur * HID + h] = acc;
                    acc = 0.f; cur++;
                }
                acc = fmaf(vv[u], sv[u], acc);
            }
        }
        for (; i < cnt; i++) {
            int r = s_r[i];
            while (cur < r) {
                out[(size_t)cur * HID + h] = acc;
                acc = 0.f; cur++;
            }
            acc = fmaf(s_v[i], __ldg(&g_support[(size_t)s_c[i] * HID + h]), acc);
        }
        __syncthreads();
    }

    // Tail flush: remaining owned rows (including trailing empty rows).
    const int rend = r0 + RPB;
    while (cur < rend) {
        out[(size_t)cur * HID + h] = acc;
        acc = 0.f; cur++;
    }
}

extern "C" void kernel_launch(void* const* d_in, const int* in_sizes, int n_in,
                              void* d_out, int out_size) {
    const float* X  = (const float*)d_in[0];  // [100000, 128]
    const int*   ar = (const int*)  d_in[1];  // adj_rows (sorted)
    const int*   ac = (const int*)  d_in[2];  // adj_cols
    const float* av = (const float*)d_in[3];  // adj_vals
    const float* W  = (const float*)d_in[4];  // [128, 128] (out, in)
    const float* b  = (const float*)d_in[5];  // [128]
    float* out = (float*)d_out;               // [100000, 128]

    cudaFuncSetAttribute(gemm_kernel,
                         cudaFuncAttributeMaxDynamicSharedMemorySize, 131072);

    int gblocks = (N_ITEMS + 127) / 128;      // 782
    gemm_kernel<<<gblocks, 256, 131072>>>(X, W, b, N_ITEMS);
    spmm_kernel<<<N_ITEMS / RPB, 128>>>(ar, ac, av, out);
}

// round 8
// speedup vs baseline: 1.3675x; 1.3675x over previous
#include <cuda_runtime.h>
#include <cuda_bf16.h>
#include <cstdint>

#define N_ITEMS 100000
#define HID 128
#define NNZ_N 1600000

// Intermediate: support = X @ W^T + b   (51.2 MB device-global scratch)
__device__ float g_support[(size_t)N_ITEMS * HID];
__device__ int   g_row_start[N_ITEMS + 1];   // CSR row pointers

// Packed fp32x2 FMA (2 FMAs / instruction on the fma pipe).
__device__ __forceinline__ unsigned long long ffma2(unsigned long long a,
                                                    unsigned long long b,
                                                    unsigned long long c) {
    unsigned long long d;
    asm("fma.rn.f32x2 %0, %1, %2, %3;" : "=l"(d) : "l"(a), "l"(b), "l"(c));
    return d;
}

// ---------------------------------------------------------------------------
// GEMM: support[n][c] = sum_k X[n][k] * W[c][k] + bias[c]
// Tile: 128 rows x 128 cols per block, 256 threads, 8x8 register tile/thread.
// Packing along K: acc holds {even-k, odd-k} partials; operands are contiguous
// k-pairs -> plain LDS.64, no repack. (Proven in R4-R6, ~fp32 FMA floor.)
// ---------------------------------------------------------------------------
extern "C" __global__ void __launch_bounds__(256)
gemm_kernel(const float* __restrict__ X, const float* __restrict__ W,
            const float* __restrict__ bias, int nrows)
{
    extern __shared__ unsigned long long smem[];
    unsigned long long* xs = smem;             // [64 k-pairs][128 rows]
    unsigned long long* ws = smem + 64 * 128;  // [64 k-pairs][128 cols]

    const int tid  = threadIdx.x;
    const int row0 = blockIdx.x * 128;

    {
        const int r      = tid >> 1;
        const int k4base = (tid & 1) * 16;
        const int grow   = row0 + r;
        const bool xok   = grow < nrows;
        const float4* xr4 = (const float4*)(X + (size_t)grow * HID);
        const float4* wr4 = (const float4*)(W + (size_t)r * HID);
        #pragma unroll
        for (int j = 0; j < 16; j++) {
            int k4 = k4base + j;
            float4 xv = xok ? xr4[k4] : make_float4(0.f, 0.f, 0.f, 0.f);
            float4 wv = wr4[k4];
            float2 x0 = make_float2(xv.x, xv.y);
            float2 x1 = make_float2(xv.z, xv.w);
            float2 w0 = make_float2(wv.x, wv.y);
            float2 w1 = make_float2(wv.z, wv.w);
            xs[(2 * k4)     * 128 + r] = *(unsigned long long*)&x0;
            xs[(2 * k4 + 1) * 128 + r] = *(unsigned long long*)&x1;
            ws[(2 * k4)     * 128 + r] = *(unsigned long long*)&w0;
            ws[(2 * k4 + 1) * 128 + r] = *(unsigned long long*)&w1;
        }
    }
    __syncthreads();

    const int tx = tid & 15;   // col group: c = tx + 16*j
    const int ty = tid >> 4;   // row group: r = ty*8 + i

    unsigned long long acc[8][8];
    #pragma unroll
    for (int i = 0; i < 8; i++)
        #pragma unroll
        for (int j = 0; j < 8; j++)
            acc[i][j] = 0ull;

    for (int k2 = 0; k2 < 64; k2++) {
        unsigned long long xv[8], wv[8];
        #pragma unroll
        for (int i = 0; i < 8; i++) xv[i] = xs[k2 * 128 + ty * 8 + i];
        #pragma unroll
        for (int j = 0; j < 8; j++) wv[j] = ws[k2 * 128 + tx + j * 16];
        #pragma unroll
        for (int i = 0; i < 8; i++)
            #pragma unroll
            for (int j = 0; j < 8; j++)
                acc[i][j] = ffma2(xv[i], wv[j], acc[i][j]);
    }

    float bv[8];
    #pragma unroll
    for (int j = 0; j < 8; j++) bv[j] = bias[tx + j * 16];

    #pragma unroll
    for (int i = 0; i < 8; i++) {
        int row = row0 + ty * 8 + i;
        if (row < nrows) {
            #pragma unroll
            for (int j = 0; j < 8; j++) {
                float2 a = *(float2*)&acc[i][j];
                g_support[(size_t)row * HID + (tx + j * 16)] = a.x + a.y + bv[j];
            }
        }
    }
}

// ---------------------------------------------------------------------------
// Row-pointer build: adj_rows sorted -> O(NNZ) boundary scan.
// ---------------------------------------------------------------------------
extern "C" __global__ void __launch_bounds__(256)
rowstart_kernel(const int* __restrict__ rows)
{
    int i = blockIdx.x * blockDim.x + threadIdx.x;
    if (i >= NNZ_N) return;
    int cur  = __ldg(rows + i);
    int prev = (i == 0) ? -1 : __ldg(rows + i - 1);
    for (int r = prev + 1; r <= cur; r++) g_row_start[r] = i;
    if (i == NNZ_N - 1)
        for (int r = cur + 1; r <= N_ITEMS; r++) g_row_start[r] = NNZ_N;
}

// ---------------------------------------------------------------------------
// SpMM: one warp per 8 rows. Lane covers 4 columns (float4 gather);
// edge (c,v) loaded 32-wide then shfl-broadcast. No searches, no atomics,
// no shared memory, fixed in-order accumulation (deterministic).
// ---------------------------------------------------------------------------
#define WR 8   // rows per warp

extern "C" __global__ void __launch_bounds__(256)
spmm_kernel(const int* __restrict__ cols, const float* __restrict__ vals,
            float* __restrict__ out)
{
    const int lane = threadIdx.x & 31;
    const int wg   = blockIdx.x * 8 + (threadIdx.x >> 5);
    const int r0   = wg * WR;
    if (r0 >= N_ITEMS) return;
    const int rend = min(r0 + WR, N_ITEMS);
    const float* sp = g_support + lane * 4;

    for (int r = r0; r < rend; r++) {
        const int s = g_row_start[r];
        const int e = g_row_start[r + 1];
        float4 acc = make_float4(0.f, 0.f, 0.f, 0.f);

        for (int i = s; i < e; ) {
            const int m = min(32, e - i);
            int   cc = 0;
            float vv = 0.f;
            if (lane < m) { cc = __ldg(cols + i + lane); vv = __ldg(vals + i + lane); }

            int u = 0;
            for (; u + 4 <= m; u += 4) {
                int c0 = __shfl_sync(0xFFFFFFFFu, cc, u);
                int c1 = __shfl_sync(0xFFFFFFFFu, cc, u + 1);
                int c2 = __shfl_sync(0xFFFFFFFFu, cc, u + 2);
                int c3 = __shfl_sync(0xFFFFFFFFu, cc, u + 3);
                float4 g0 = *(const float4*)(sp + (size_t)c0 * HID);
                float4 g1 = *(const float4*)(sp + (size_t)c1 * HID);
                float4 g2 = *(const float4*)(sp + (size_t)c2 * HID);
                float4 g3 = *(const float4*)(sp + (size_t)c3 * HID);
                float v0 = __shfl_sync(0xFFFFFFFFu, vv, u);
                float v1 = __shfl_sync(0xFFFFFFFFu, vv, u + 1);
                float v2 = __shfl_sync(0xFFFFFFFFu, vv, u + 2);
                float v3 = __shfl_sync(0xFFFFFFFFu, vv, u + 3);
                acc.x = fmaf(v0, g0.x, acc.x); acc.y = fmaf(v0, g0.y, acc.y);
                acc.z = fmaf(v0, g0.z, acc.z); acc.w = fmaf(v0, g0.w, acc.w);
                acc.x = fmaf(v1, g1.x, acc.x); acc.y = fmaf(v1, g1.y, acc.y);
                acc.z = fmaf(v1, g1.z, acc.z); acc.w = fmaf(v1, g1.w, acc.w);
                acc.x = fmaf(v2, g2.x, acc.x); acc.y = fmaf(v2, g2.y, acc.y);
                acc.z = fmaf(v2, g2.z, acc.z); acc.w = fmaf(v2, g2.w, acc.w);
                acc.x = fmaf(v3, g3.x, acc.x); acc.y = fmaf(v3, g3.y, acc.y);
                acc.z = fmaf(v3, g3.z, acc.z); acc.w = fmaf(v3, g3.w, acc.w);
            }
            for (; u < m; u++) {
                int   c = __shfl_sync(0xFFFFFFFFu, cc, u);
                float v = __shfl_sync(0xFFFFFFFFu, vv, u);
                float4 g = *(const float4*)(sp + (size_t)c * HID);
                acc.x = fmaf(v, g.x, acc.x); acc.y = fmaf(v, g.y, acc.y);
                acc.z = fmaf(v, g.z, acc.z); acc.w = fmaf(v, g.w, acc.w);
            }
            i += m;
        }
        *(float4*)(out + (size_t)r * HID + lane * 4) = acc;
    }
}

// ---------------------------------------------------------------------------
extern "C" void kernel_launch(void* const* d_in, const int* in_sizes, int n_in,
                              void* d_out, int out_size) {
    const float* X  = (const float*)d_in[0];  // [100000, 128]
    const int*   ar = (const int*)  d_in[1];  // adj_rows (sorted)
    const int*   ac = (const int*)  d_in[2];  // adj_cols
    const float* av = (const float*)d_in[3];  // adj_vals
    const float* W  = (const float*)d_in[4];  // [128, 128] (out, in)
    const float* b  = (const float*)d_in[5];  // [128]
    float* out = (float*)d_out;               // [100000, 128]

    cudaFuncSetAttribute(gemm_kernel,
                         cudaFuncAttributeMaxDynamicSharedMemorySize, 131072);

    const int gblocks = (N_ITEMS + 127) / 128;               // 782
    gemm_kernel<<<gblocks, 256, 131072>>>(X, W, b, N_ITEMS);

    rowstart_kernel<<<(NNZ_N + 255) / 256, 256>>>(ar);

    const int sblocks = (N_ITEMS + 8 * WR - 1) / (8 * WR);   // 1563
    spmm_kernel<<<sblocks, 256>>>(ac, av, out);
}

// round 9
// speedup vs baseline: 1.8026x; 1.3181x over previous
#include <cuda_runtime.h>
#include <cuda_bf16.h>
#include <cstdint>

#define N_ITEMS 100000
#define HID 128
#define NNZ_N 1600000

// Intermediate: support = X @ W^T + b   (51.2 MB device-global scratch)
__device__ float g_support[(size_t)N_ITEMS * HID];
__device__ int   g_row_start[N_ITEMS + 1];   // CSR row pointers

// ---------------------------------------------------------------------------
// PTX helpers (all stable ISA — valid for plain sm_103 ptxas target)
// ---------------------------------------------------------------------------
__device__ __forceinline__ uint32_t smem_u32(const void* p) {
    uint32_t a;
    asm("{ .reg .u64 t; cvta.to.shared.u64 t, %1; cvt.u32.u64 %0, t; }"
        : "=r"(a) : "l"(p));
    return a;
}

__device__ __forceinline__ void ldsm4(uint32_t* r, uint32_t addr) {
    asm volatile("ldmatrix.sync.aligned.m8n8.x4.shared.b16 {%0,%1,%2,%3}, [%4];"
        : "=r"(r[0]), "=r"(r[1]), "=r"(r[2]), "=r"(r[3]) : "r"(addr));
}

__device__ __forceinline__ void mma16816(float* d, const uint32_t* a,
                                         uint32_t b0, uint32_t b1) {
    asm volatile("mma.sync.aligned.m16n8k16.row.col.f32.bf16.bf16.f32 "
        "{%0,%1,%2,%3}, {%4,%5,%6,%7}, {%8,%9}, {%0,%1,%2,%3};"
        : "+f"(d[0]), "+f"(d[1]), "+f"(d[2]), "+f"(d[3])
        : "r"(a[0]), "r"(a[1]), "r"(a[2]), "r"(a[3]), "r"(b0), "r"(b1));
}

// Split a float4 into hi/lo bf16x4 (8B each). hi = rn(bf16); lo = rn(x - hi).
__device__ __forceinline__ void split4(float4 v, uint2& hu, uint2& lu) {
    __nv_bfloat16 h0 = __float2bfloat16(v.x), h1 = __float2bfloat16(v.y);
    __nv_bfloat16 h2 = __float2bfloat16(v.z), h3 = __float2bfloat16(v.w);
    __nv_bfloat16 l0 = __float2bfloat16(v.x - __bfloat162float(h0));
    __nv_bfloat16 l1 = __float2bfloat16(v.y - __bfloat162float(h1));
    __nv_bfloat16 l2 = __float2bfloat16(v.z - __bfloat162float(h2));
    __nv_bfloat16 l3 = __float2bfloat16(v.w - __bfloat162float(h3));
    __nv_bfloat162 hp0 = {h0, h1}, hp1 = {h2, h3};
    __nv_bfloat162 lp0 = {l0, l1}, lp1 = {l2, l3};
    hu.x = *(uint32_t*)&hp0; hu.y = *(uint32_t*)&hp1;
    lu.x = *(uint32_t*)&lp0; lu.y = *(uint32_t*)&lp1;
}

// ---------------------------------------------------------------------------
// GEMM: support = X @ W^T + b via bf16 2-split mma.sync, fp32 accumulate.
// CTA tile 128x128, K=128; 8 warps, warp tile 32m x 64n.
// smem tiles padded to 136 bf16/row (272B) -> ldmatrix conflict-free.
// ---------------------------------------------------------------------------
#define SA 136
#define TILE_E (128 * SA)
#define GEMM_SMEM (4 * TILE_E * 2)   // Ah, Al, Bh, Bl = 139264 B

extern "C" __global__ void __launch_bounds__(256)
gemm_mma_kernel(const float* __restrict__ X, const float* __restrict__ W,
                const float* __restrict__ bias, int nrows)
{
    extern __shared__ __nv_bfloat16 sm[];
    __nv_bfloat16* Ah = sm;
    __nv_bfloat16* Al = Ah + TILE_E;
    __nv_bfloat16* Bh = Al + TILE_E;
    __nv_bfloat16* Bl = Bh + TILE_E;

    const int tid  = threadIdx.x;
    const int lane = tid & 31;
    const int wid  = tid >> 5;
    const int row0 = blockIdx.x * 128;

    // ---- load + split-convert X tile and W into bf16 hi/lo smem tiles ----
    {
        const int r    = tid >> 1;
        const int c0   = (tid & 1) * 64;
        const int grow = row0 + r;
        const bool ok  = grow < nrows;
        const float4* xp = (const float4*)(X + (size_t)grow * HID + c0);
        const float4* wp = (const float4*)(W + (size_t)r * HID + c0);
        #pragma unroll
        for (int j = 0; j < 16; j++) {
            float4 xv = ok ? xp[j] : make_float4(0.f, 0.f, 0.f, 0.f);
            uint2 hu, lu;
            split4(xv, hu, lu);
            int off = r * SA + c0 + j * 4;
            *(uint2*)(Ah + off) = hu;
            *(uint2*)(Al + off) = lu;
            float4 wv = wp[j];
            split4(wv, hu, lu);
            *(uint2*)(Bh + off) = hu;
            *(uint2*)(Bl + off) = lu;
        }
    }
    __syncthreads();

    // ---- mma mainloop: 3 split passes (AhBh, AhBl, AlBh) x 8 k16 steps ----
    const int wm = (wid & 3) * 32;       // warp m offset
    const int wn = (wid >> 2) * 64;      // warp n offset

    float acc[2][8][4];
    #pragma unroll
    for (int i = 0; i < 2; i++)
        #pragma unroll
        for (int j = 0; j < 8; j++)
            #pragma unroll
            for (int q = 0; q < 4; q++) acc[i][j][q] = 0.f;

    // per-lane element offsets (in bf16 units) for ldmatrix.x4
    const uint32_t a_lane = (uint32_t)((wm + (lane & 15)) * SA + ((lane >> 4) << 3));
    const uint32_t b_lane = (uint32_t)((wn + ((lane >> 4) << 3) + (lane & 7)) * SA
                                       + (((lane >> 3) & 1) << 3));
    const uint32_t ah_b = smem_u32(Ah), al_b = smem_u32(Al);
    const uint32_t bh_b = smem_u32(Bh), bl_b = smem_u32(Bl);

    #pragma unroll 1
    for (int s = 0; s < 3; s++) {
        const uint32_t Ab = (s == 2) ? al_b : ah_b;
        const uint32_t Bb = (s == 1) ? bl_b : bh_b;
        #pragma unroll
        for (int k = 0; k < 128; k += 16) {
            uint32_t ra[2][4], rb[4][4];
            uint32_t aaddr = Ab + (a_lane + k) * 2;
            ldsm4(ra[0], aaddr);
            ldsm4(ra[1], aaddr + 16 * SA * 2);
            uint32_t baddr = Bb + (b_lane + k) * 2;
            #pragma unroll
            for (int g = 0; g < 4; g++)
                ldsm4(rb[g], baddr + g * 16 * SA * 2);
            #pragma unroll
            for (int mi = 0; mi < 2; mi++)
                #pragma unroll
                for (int g = 0; g < 4; g++) {
                    mma16816(acc[mi][2 * g],     ra[mi], rb[g][0], rb[g][1]);
                    mma16816(acc[mi][2 * g + 1], ra[mi], rb[g][2], rb[g][3]);
                }
        }
    }

    // ---- epilogue: add bias, write fp32 support ----
    const int lrow = lane >> 2;
    const int lcol = (lane & 3) * 2;
    float2 bv[8];
    #pragma unroll
    for (int nj = 0; nj < 8; nj++) {
        int c = wn + nj * 8 + lcol;
        bv[nj].x = __ldg(bias + c);
        bv[nj].y = __ldg(bias + c + 1);
    }
    #pragma unroll
    for (int mi = 0; mi < 2; mi++) {
        int r1 = row0 + wm + mi * 16 + lrow;
        int r2 = r1 + 8;
        #pragma unroll
        for (int nj = 0; nj < 8; nj++) {
            int c = wn + nj * 8 + lcol;
            if (r1 < nrows) {
                float2 o = {acc[mi][nj][0] + bv[nj].x, acc[mi][nj][1] + bv[nj].y};
                *(float2*)&g_support[(size_t)r1 * HID + c] = o;
            }
            if (r2 < nrows) {
                float2 o = {acc[mi][nj][2] + bv[nj].x, acc[mi][nj][3] + bv[nj].y};
                *(float2*)&g_support[(size_t)r2 * HID + c] = o;
            }
        }
    }
}

// ---------------------------------------------------------------------------
// Row-pointer build: adj_rows sorted -> O(NNZ) boundary scan.
// ---------------------------------------------------------------------------
extern "C" __global__ void __launch_bounds__(256)
rowstart_kernel(const int* __restrict__ rows)
{
    int i = blockIdx.x * blockDim.x + threadIdx.x;
    if (i >= NNZ_N) return;
    int cur  = __ldg(rows + i);
    int prev = (i == 0) ? -1 : __ldg(rows + i - 1);
    for (int r = prev + 1; r <= cur; r++) g_row_start[r] = i;
    if (i == NNZ_N - 1)
        for (int r = cur + 1; r <= N_ITEMS; r++) g_row_start[r] = NNZ_N;
}

// ---------------------------------------------------------------------------
// SpMM: one warp per 8 rows. Lane covers 4 columns (float4 gather);
// edge (c,v) loaded 32-wide then shfl-broadcast. No searches, no atomics,
// deterministic in-order accumulation.  (Measured-good in R8.)
// ---------------------------------------------------------------------------
#define WR 8   // rows per warp

extern "C" __global__ void __launch_bounds__(256)
spmm_kernel(const int* __restrict__ cols, const float* __restrict__ vals,
            float* __restrict__ out)
{
    const int lane = threadIdx.x & 31;
    const int wg   = blockIdx.x * 8 + (threadIdx.x >> 5);
    const int r0   = wg * WR;
    if (r0 >= N_ITEMS) return;
    const int rend = min(r0 + WR, N_ITEMS);
    const float* sp = g_support + lane * 4;

    for (int r = r0; r < rend; r++) {
        const int s = g_row_start[r];
        const int e = g_row_start[r + 1];
        float4 acc = make_float4(0.f, 0.f, 0.f, 0.f);

        for (int i = s; i < e; ) {
            const int m = min(32, e - i);
            int   cc = 0;
            float vv = 0.f;
            if (lane < m) { cc = __ldg(cols + i + lane); vv = __ldg(vals + i + lane); }

            int u = 0;
            for (; u + 4 <= m; u += 4) {
                int c0 = __shfl_sync(0xFFFFFFFFu, cc, u);
                int c1 = __shfl_sync(0xFFFFFFFFu, cc, u + 1);
                int c2 = __shfl_sync(0xFFFFFFFFu, cc, u + 2);
                int c3 = __shfl_sync(0xFFFFFFFFu, cc, u + 3);
                float4 g0 = *(const float4*)(sp + (size_t)c0 * HID);
                float4 g1 = *(const float4*)(sp + (size_t)c1 * HID);
                float4 g2 = *(const float4*)(sp + (size_t)c2 * HID);
                float4 g3 = *(const float4*)(sp + (size_t)c3 * HID);
                float v0 = __shfl_sync(0xFFFFFFFFu, vv, u);
                float v1 = __shfl_sync(0xFFFFFFFFu, vv, u + 1);
                float v2 = __shfl_sync(0xFFFFFFFFu, vv, u + 2);
                float v3 = __shfl_sync(0xFFFFFFFFu, vv, u + 3);
                acc.x = fmaf(v0, g0.x, acc.x); acc.y = fmaf(v0, g0.y, acc.y);
                acc.z = fmaf(v0, g0.z, acc.z); acc.w = fmaf(v0, g0.w, acc.w);
                acc.x = fmaf(v1, g1.x, acc.x); acc.y = fmaf(v1, g1.y, acc.y);
                acc.z = fmaf(v1, g1.z, acc.z); acc.w = fmaf(v1, g1.w, acc.w);
                acc.x = fmaf(v2, g2.x, acc.x); acc.y = fmaf(v2, g2.y, acc.y);
                acc.z = fmaf(v2, g2.z, acc.z); acc.w = fmaf(v2, g2.w, acc.w);
                acc.x = fmaf(v3, g3.x, acc.x); acc.y = fmaf(v3, g3.y, acc.y);
                acc.z = fmaf(v3, g3.z, acc.z); acc.w = fmaf(v3, g3.w, acc.w);
            }
            for (; u < m; u++) {
                int   c = __shfl_sync(0xFFFFFFFFu, cc, u);
                float v = __shfl_sync(0xFFFFFFFFu, vv, u);
                float4 g = *(const float4*)(sp + (size_t)c * HID);
                acc.x = fmaf(v, g.x, acc.x); acc.y = fmaf(v, g.y, acc.y);
                acc.z = fmaf(v, g.z, acc.z); acc.w = fmaf(v, g.w, acc.w);
            }
            i += m;
        }
        *(float4*)(out + (size_t)r * HID + lane * 4) = acc;
    }
}

// ---------------------------------------------------------------------------
extern "C" void kernel_launch(void* const* d_in, const int* in_sizes, int n_in,
                              void* d_out, int out_size) {
    const float* X  = (const float*)d_in[0];  // [100000, 128]
    const int*   ar = (const int*)  d_in[1];  // adj_rows (sorted)
    const int*   ac = (const int*)  d_in[2];  // adj_cols
    const float* av = (const float*)d_in[3];  // adj_vals
    const float* W  = (const float*)d_in[4];  // [128, 128] (out, in)
    const float* b  = (const float*)d_in[5];  // [128]
    float* out = (float*)d_out;               // [100000, 128]

    cudaFuncSetAttribute(gemm_mma_kernel,
                         cudaFuncAttributeMaxDynamicSharedMemorySize, GEMM_SMEM);

    const int gblocks = (N_ITEMS + 127) / 128;               // 782
    gemm_mma_kernel<<<gblocks, 256, GEMM_SMEM>>>(X, W, b, N_ITEMS);

    rowstart_kernel<<<(NNZ_N + 255) / 256, 256>>>(ar);

    const int sblocks = (N_ITEMS + 8 * WR - 1) / (8 * WR);   // 1563
    spmm_kernel<<<sblocks, 256>>>(ac, av, out);
}